// round 7
// baseline (speedup 1.0000x reference)
#include <cuda_runtime.h>
#include <cstdint>
#include <math.h>

#define T_SEQ 16384
#define HDIM  512
#define G4    2048
#define NB    128     // CTAs in the recurrent kernel (<= 148, all co-resident)
#define UPB   4       // hidden units per CTA  (NB * UPB == HDIM)

// Scratch (static __device__ arrays are the allocation-guard-legal scratch path)
__device__ float g_xgates[(size_t)T_SEQ * G4];   // 128 MB precomputed input gates
// Tagged h broadcast ring: g_htag[slot][unit] = {h_value_bits, step_tag (t+1)}
// Single 8B *morally strong* (relaxed.gpu) store/load: the tag IS the sync.
__device__ __align__(16) unsigned long long g_htag[2][HDIM];

// ---------------------------------------------------------------------------
// Prologue: zero the tag ring every launch (graph replays reuse tag values)
// ---------------------------------------------------------------------------
__global__ void zero_tags_kernel() {
    int i = blockIdx.x * blockDim.x + threadIdx.x;
    if (i < 2 * HDIM) ((unsigned long long*)g_htag)[i] = 0ULL;
}

// ---------------------------------------------------------------------------
// GEMM: g_xgates[t][j] = dot(input[t,:], w_ih[j,:]) + b_ih[j]
// 128x128 block tile, BK=8, 256 threads, 8x8 per-thread tile. Full fp32 FMA.
// ---------------------------------------------------------------------------
__global__ __launch_bounds__(256) void gemm_xgates_kernel(
    const float* __restrict__ A, const float* __restrict__ W,
    const float* __restrict__ bias)
{
    __shared__ float As[8][128];
    __shared__ float Ws[8][128];
    const int bm = blockIdx.y * 128;   // along T
    const int bn = blockIdx.x * 128;   // along 4H
    const int tid = threadIdx.x;
    const int lr = tid >> 1;           // 0..127 tile row for loads
    const int lc = (tid & 1) << 2;     // 0 or 4 (float4 column)
    const int tx = tid & 15;
    const int ty = tid >> 4;

    float acc[8][8];
#pragma unroll
    for (int i = 0; i < 8; i++)
#pragma unroll
        for (int j = 0; j < 8; j++) acc[i][j] = 0.0f;

    const float* Aptr = A + (size_t)(bm + lr) * HDIM + lc;
    const float* Wptr = W + (size_t)(bn + lr) * HDIM + lc;

    for (int k0 = 0; k0 < HDIM; k0 += 8) {
        float4 av = *(const float4*)(Aptr + k0);
        float4 wv = *(const float4*)(Wptr + k0);
        __syncthreads();   // guard previous iteration's smem reads
        As[lc + 0][lr] = av.x; As[lc + 1][lr] = av.y;
        As[lc + 2][lr] = av.z; As[lc + 3][lr] = av.w;
        Ws[lc + 0][lr] = wv.x; Ws[lc + 1][lr] = wv.y;
        Ws[lc + 2][lr] = wv.z; Ws[lc + 3][lr] = wv.w;
        __syncthreads();
#pragma unroll
        for (int k = 0; k < 8; k++) {
            float a[8], b[8];
            *(float4*)(a)     = *(const float4*)&As[k][ty * 8];
            *(float4*)(a + 4) = *(const float4*)&As[k][ty * 8 + 4];
            *(float4*)(b)     = *(const float4*)&Ws[k][tx * 8];
            *(float4*)(b + 4) = *(const float4*)&Ws[k][tx * 8 + 4];
#pragma unroll
            for (int i = 0; i < 8; i++)
#pragma unroll
                for (int j = 0; j < 8; j++)
                    acc[i][j] = fmaf(a[i], b[j], acc[i][j]);
        }
    }

    float bb[8];
    *(float4*)(bb)     = *(const float4*)&bias[bn + tx * 8];
    *(float4*)(bb + 4) = *(const float4*)&bias[bn + tx * 8 + 4];
#pragma unroll
    for (int i = 0; i < 8; i++) {
        float* cp = g_xgates + (size_t)(bm + ty * 8 + i) * G4 + bn + tx * 8;
        float4 v0 = make_float4(acc[i][0] + bb[0], acc[i][1] + bb[1],
                                acc[i][2] + bb[2], acc[i][3] + bb[3]);
        float4 v1 = make_float4(acc[i][4] + bb[4], acc[i][5] + bb[5],
                                acc[i][6] + bb[6], acc[i][7] + bb[7]);
        *(float4*)cp       = v0;
        *(float4*)(cp + 4) = v1;
    }
}

// ---------------------------------------------------------------------------
// Recurrent persistent kernel — R6 skeleton (2 barriers/step, single hs
// buffer, MUFU activations, v4 polls) + xg loads software-pipelined one
// step ahead (the ONLY change vs R6: hides the ~600-1000cyc DRAM latency
// of the scattered gate-preactivation load behind a full step period).
// ---------------------------------------------------------------------------
// MUFU-based activations. End-to-end validated: rel_err 4.43e-7.
__device__ __forceinline__ float sigmoid_fast(float x) {
    return __fdividef(1.0f, 1.0f + __expf(-x));
}
__device__ __forceinline__ float tanh_fast(float x) {
    return 1.0f - __fdividef(2.0f, __expf(2.0f * x) + 1.0f);
}

// morally strong ops at gpu scope (tag as integer bits end-to-end)
__device__ __forceinline__ void ld_relaxed_v4(const unsigned long long* p,
                                              unsigned int& a, unsigned int& b,
                                              unsigned int& c, unsigned int& d) {
    asm volatile("ld.relaxed.gpu.global.v4.b32 {%0,%1,%2,%3}, [%4];"
                 : "=r"(a), "=r"(b), "=r"(c), "=r"(d) : "l"(p) : "memory");
}
__device__ __forceinline__ void st_relaxed_v2(unsigned long long* p,
                                              unsigned int v, unsigned int tg) {
    asm volatile("st.relaxed.gpu.global.v2.b32 [%0], {%1,%2};"
                 :: "l"(p), "r"(v), "r"(tg) : "memory");
}

// pad every 16-float group by 4 -> conflict-free LDS.128 at stride 20
#define PADIDX(i) ((i) + (((i) >> 4) << 2))

__global__ void __launch_bounds__(128, 1) lstm_rec_kernel(
    const float* __restrict__ Whh, float* __restrict__ out)
{
    const int b   = blockIdx.x;
    const int tid = threadIdx.x;
    const int w   = tid >> 5;   // warp = owned unit index (0..3)
    const int l   = tid & 31;

    __shared__ float hs[640];   // 512 + padding

    // Preload W_hh rows: wt[gate][k] for unit gu = 4b+w, cols 16l..16l+15
    const int gu = b * UPB + w;
    float wt[4][16];
#pragma unroll
    for (int g = 0; g < 4; g++) {
        const float* row = Whh + (size_t)(g * HDIM + gu) * HDIM + l * 16;
#pragma unroll
        for (int kk = 0; kk < 16; kk += 4) {
            float4 v = *(const float4*)(row + kk);
            wt[g][kk] = v.x; wt[g][kk + 1] = v.y;
            wt[g][kk + 2] = v.z; wt[g][kk + 3] = v.w;
        }
    }

    for (int i = tid; i < 640; i += 128) hs[i] = 0.0f;  // h_{-1} = 0
    float c_state = 0.0f;                               // lane 0 of each warp
    __syncthreads();

    // Software-pipelined xg: lanes 0-3 hold one gate pre-activation each,
    // loaded ONE FULL STEP ahead of use.
    const bool xlane = (l < 4);
    const float* xbase = g_xgates + (size_t)l * HDIM + gu;  // valid for l<4
    float xg_cur = 0.0f;
    if (xlane) {
        asm volatile("ld.global.cs.b32 %0, [%1];" : "=f"(xg_cur) : "l"(xbase));
    }

    for (int t = 0; t < T_SEQ; t++) {
        // Issue next step's xg load immediately: covered by poll+compute+barriers
        float xg_nxt = 0.0f;
        if (xlane) {
            const float* xr = xbase + (size_t)((t + 1 < T_SEQ) ? t + 1 : t) * G4;
            asm volatile("ld.global.cs.b32 %0, [%1];" : "=f"(xg_nxt) : "l"(xr));
        }

        if (t > 0) {
            // Poll own 4 tagged words of h_{t-1} (one 32B sector) with 2 v4 loads
            const unsigned long long* hp = &g_htag[(t - 1) & 1][tid * 4];
            const unsigned int tagv = (unsigned int)t;  // producer tag = (t-1)+1
            unsigned int v0, v1, v2, v3, g0, g1, g2, g3;
            while (true) {
                ld_relaxed_v4(hp + 0, v0, g0, v1, g1);
                ld_relaxed_v4(hp + 2, v2, g2, v3, g3);
                if (g0 == tagv && g1 == tagv && g2 == tagv && g3 == tagv)
                    break;
            }
            float4 hv = make_float4(__uint_as_float(v0), __uint_as_float(v1),
                                    __uint_as_float(v2), __uint_as_float(v3));
            *(float4*)&hs[PADIDX(tid * 4)] = hv;
            __syncthreads();   // barrier A: all 512 h values staged
        }

        // Matvec: 4 gate rows x 16 cols per lane
        float hv16[16];
        const float* hrow = &hs[20 * l];
#pragma unroll
        for (int kk = 0; kk < 16; kk += 4)
            *(float4*)(hv16 + kk) = *(const float4*)(hrow + kk);

        float a0 = 0.f, a1 = 0.f, a2 = 0.f, a3 = 0.f;
#pragma unroll
        for (int kk = 0; kk < 16; kk++) {
            a0 = fmaf(wt[0][kk], hv16[kk], a0);
            a1 = fmaf(wt[1][kk], hv16[kk], a1);
            a2 = fmaf(wt[2][kk], hv16[kk], a2);
            a3 = fmaf(wt[3][kk], hv16[kk], a3);
        }
        // Full butterfly: all lanes end with the complete 4 gate sums
#pragma unroll
        for (int off = 16; off >= 1; off >>= 1) {
            a0 += __shfl_xor_sync(0xffffffffu, a0, off);
            a1 += __shfl_xor_sync(0xffffffffu, a1, off);
            a2 += __shfl_xor_sync(0xffffffffu, a2, off);
            a3 += __shfl_xor_sync(0xffffffffu, a3, off);
        }

        // Lanes 0-3 apply their gate's activation in parallel (MUFU path)
        float act = 0.0f;
        if (xlane) {
            float pre = (l == 0 ? a0 : l == 1 ? a1 : l == 2 ? a2 : a3) + xg_cur;
            act = (l == 2) ? tanh_fast(pre) : sigmoid_fast(pre);
        }
        float iv = __shfl_sync(0xffffffffu, act, 0);
        float fv = __shfl_sync(0xffffffffu, act, 1);
        float gv = __shfl_sync(0xffffffffu, act, 2);
        float ov = __shfl_sync(0xffffffffu, act, 3);

        if (l == 0) {
            c_state = fv * c_state + iv * gv;
            float hval = ov * tanh_fast(c_state);
            // Publish {h, tag=t+1}: ONE morally-strong 8B store = the signal
            st_relaxed_v2(&g_htag[t & 1][gu], __float_as_uint(hval),
                          (unsigned int)(t + 1));
            out[(size_t)t * HDIM + gu] = hval;
        }
        xg_cur = xg_nxt;
        __syncthreads();   // trailing barrier: re-aligns warps each step
    }
}

// ---------------------------------------------------------------------------
extern "C" void kernel_launch(void* const* d_in, const int* in_sizes, int n_in,
                              void* d_out, int out_size) {
    const float* input = (const float*)d_in[0];  // [T, H]
    const float* w_ih  = (const float*)d_in[1];  // [4H, H]
    const float* w_hh  = (const float*)d_in[2];  // [4H, H]
    const float* b_ih  = (const float*)d_in[3];  // [4H]
    float* out = (float*)d_out;                  // [T, H]
    (void)in_sizes; (void)n_in; (void)out_size;

    zero_tags_kernel<<<4, 256>>>();

    dim3 gg(G4 / 128, T_SEQ / 128);              // 16 x 128 blocks
    gemm_xgates_kernel<<<gg, 256>>>(input, w_ih, b_ih);

    lstm_rec_kernel<<<NB, 128>>>(w_hh, out);
}

// round 8
// speedup vs baseline: 1.0080x; 1.0080x over previous
#include <cuda_runtime.h>
#include <cstdint>
#include <math.h>

#define T_SEQ 16384
#define HDIM  512
#define G4    2048
#define NB    128     // CTAs in the recurrent kernel (<= 148, all co-resident)
#define UPB   4       // hidden units per CTA  (NB * UPB == HDIM)

// Scratch (static __device__ arrays are the allocation-guard-legal scratch path)
__device__ float g_xgates[(size_t)T_SEQ * G4];   // 128 MB precomputed input gates
// Parity-packed h broadcast ring: g_hpar[slot][unit] is h with its mantissa
// LSB forced to parity((t)) = (t>>1)&1.  The LSB IS the sync tag: a single
// 4B morally-strong store publishes value+phase atomically, and consumers
// poll 4 units with ONE 16B relaxed load (halves the L2 poll request storm).
__device__ __align__(16) unsigned int g_hpar[2][HDIM];

// ---------------------------------------------------------------------------
// Prologue: init ring with LSB=1 (never matches the first expected parity 0)
// ---------------------------------------------------------------------------
__global__ void init_ring_kernel() {
    int i = blockIdx.x * blockDim.x + threadIdx.x;
    if (i < 2 * HDIM) ((unsigned int*)g_hpar)[i] = 1u;  // denormal, LSB=1
}

// ---------------------------------------------------------------------------
// GEMM: g_xgates[t][j] = dot(input[t,:], w_ih[j,:]) + b_ih[j]
// 128x128 block tile, BK=8, 256 threads, 8x8 per-thread tile. Full fp32 FMA.
// ---------------------------------------------------------------------------
__global__ __launch_bounds__(256) void gemm_xgates_kernel(
    const float* __restrict__ A, const float* __restrict__ W,
    const float* __restrict__ bias)
{
    __shared__ float As[8][128];
    __shared__ float Ws[8][128];
    const int bm = blockIdx.y * 128;   // along T
    const int bn = blockIdx.x * 128;   // along 4H
    const int tid = threadIdx.x;
    const int lr = tid >> 1;           // 0..127 tile row for loads
    const int lc = (tid & 1) << 2;     // 0 or 4 (float4 column)
    const int tx = tid & 15;
    const int ty = tid >> 4;

    float acc[8][8];
#pragma unroll
    for (int i = 0; i < 8; i++)
#pragma unroll
        for (int j = 0; j < 8; j++) acc[i][j] = 0.0f;

    const float* Aptr = A + (size_t)(bm + lr) * HDIM + lc;
    const float* Wptr = W + (size_t)(bn + lr) * HDIM + lc;

    for (int k0 = 0; k0 < HDIM; k0 += 8) {
        float4 av = *(const float4*)(Aptr + k0);
        float4 wv = *(const float4*)(Wptr + k0);
        __syncthreads();   // guard previous iteration's smem reads
        As[lc + 0][lr] = av.x; As[lc + 1][lr] = av.y;
        As[lc + 2][lr] = av.z; As[lc + 3][lr] = av.w;
        Ws[lc + 0][lr] = wv.x; Ws[lc + 1][lr] = wv.y;
        Ws[lc + 2][lr] = wv.z; Ws[lc + 3][lr] = wv.w;
        __syncthreads();
#pragma unroll
        for (int k = 0; k < 8; k++) {
            float a[8], b[8];
            *(float4*)(a)     = *(const float4*)&As[k][ty * 8];
            *(float4*)(a + 4) = *(const float4*)&As[k][ty * 8 + 4];
            *(float4*)(b)     = *(const float4*)&Ws[k][tx * 8];
            *(float4*)(b + 4) = *(const float4*)&Ws[k][tx * 8 + 4];
#pragma unroll
            for (int i = 0; i < 8; i++)
#pragma unroll
                for (int j = 0; j < 8; j++)
                    acc[i][j] = fmaf(a[i], b[j], acc[i][j]);
        }
    }

    float bb[8];
    *(float4*)(bb)     = *(const float4*)&bias[bn + tx * 8];
    *(float4*)(bb + 4) = *(const float4*)&bias[bn + tx * 8 + 4];
#pragma unroll
    for (int i = 0; i < 8; i++) {
        float* cp = g_xgates + (size_t)(bm + ty * 8 + i) * G4 + bn + tx * 8;
        float4 v0 = make_float4(acc[i][0] + bb[0], acc[i][1] + bb[1],
                                acc[i][2] + bb[2], acc[i][3] + bb[3]);
        float4 v1 = make_float4(acc[i][4] + bb[4], acc[i][5] + bb[5],
                                acc[i][6] + bb[6], acc[i][7] + bb[7]);
        *(float4*)cp       = v0;
        *(float4*)(cp + 4) = v1;
    }
}

// ---------------------------------------------------------------------------
// Recurrent persistent kernel — R6/R7 skeleton (2 barriers/step, single hs
// buffer, MUFU activations, xg pipelined). ONLY protocol change vs R7:
// parity-packed 4B publishes + single 16B polls (halves L2 poll incast).
// ---------------------------------------------------------------------------
// MUFU-based activations. End-to-end validated: rel_err 4.4e-7.
__device__ __forceinline__ float sigmoid_fast(float x) {
    return __fdividef(1.0f, 1.0f + __expf(-x));
}
__device__ __forceinline__ float tanh_fast(float x) {
    return 1.0f - __fdividef(2.0f, __expf(2.0f * x) + 1.0f);
}

// morally strong ops at gpu scope
__device__ __forceinline__ void ld_relaxed_v4u(const unsigned int* p,
                                               unsigned int& a, unsigned int& b,
                                               unsigned int& c, unsigned int& d) {
    asm volatile("ld.relaxed.gpu.global.v4.b32 {%0,%1,%2,%3}, [%4];"
                 : "=r"(a), "=r"(b), "=r"(c), "=r"(d) : "l"(p) : "memory");
}
__device__ __forceinline__ void st_relaxed_u32(unsigned int* p, unsigned int v) {
    asm volatile("st.relaxed.gpu.global.b32 [%0], %1;" :: "l"(p), "r"(v) : "memory");
}

// pad every 16-float group by 4 -> conflict-free LDS.128 at stride 20
#define PADIDX(i) ((i) + (((i) >> 4) << 2))

__global__ void __launch_bounds__(128, 1) lstm_rec_kernel(
    const float* __restrict__ Whh, float* __restrict__ out)
{
    const int b   = blockIdx.x;
    const int tid = threadIdx.x;
    const int w   = tid >> 5;   // warp = owned unit index (0..3)
    const int l   = tid & 31;

    __shared__ float hs[640];   // 512 + padding

    // Preload W_hh rows: wt[gate][k] for unit gu = 4b+w, cols 16l..16l+15
    const int gu = b * UPB + w;
    float wt[4][16];
#pragma unroll
    for (int g = 0; g < 4; g++) {
        const float* row = Whh + (size_t)(g * HDIM + gu) * HDIM + l * 16;
#pragma unroll
        for (int kk = 0; kk < 16; kk += 4) {
            float4 v = *(const float4*)(row + kk);
            wt[g][kk] = v.x; wt[g][kk + 1] = v.y;
            wt[g][kk + 2] = v.z; wt[g][kk + 3] = v.w;
        }
    }

    for (int i = tid; i < 640; i += 128) hs[i] = 0.0f;  // h_{-1} = 0
    float c_state = 0.0f;                               // lane 0 of each warp
    __syncthreads();

    // Software-pipelined xg: lanes 0-3 hold one gate pre-activation each,
    // loaded one full step ahead of use.
    const bool xlane = (l < 4);
    const float* xbase = g_xgates + (size_t)l * HDIM + gu;  // valid for l<4
    float xg_cur = 0.0f;
    if (xlane) {
        asm volatile("ld.global.cs.b32 %0, [%1];" : "=f"(xg_cur) : "l"(xbase));
    }

    for (int t = 0; t < T_SEQ; t++) {
        // Issue next step's xg load immediately (covered by poll + compute)
        float xg_nxt = 0.0f;
        if (xlane) {
            const float* xr = xbase + (size_t)((t + 1 < T_SEQ) ? t + 1 : t) * G4;
            asm volatile("ld.global.cs.b32 %0, [%1];" : "=f"(xg_nxt) : "l"(xr));
        }

        if (t > 0) {
            // Poll own 4 units of h_{t-1}: ONE 16B relaxed load per iteration.
            // Expected phase parity of step t-1 = ((t-1)>>1)&1 in each LSB.
            const unsigned int* hp = &g_hpar[(t - 1) & 1][tid * 4];
            const unsigned int par = ((unsigned int)(t - 1) >> 1) & 1u;
            unsigned int v0, v1, v2, v3;
            while (true) {
                ld_relaxed_v4u(hp, v0, v1, v2, v3);
                if (((v0 ^ par) & 1u) == 0u && ((v1 ^ par) & 1u) == 0u &&
                    ((v2 ^ par) & 1u) == 0u && ((v3 ^ par) & 1u) == 0u)
                    break;
            }
            float4 hv = make_float4(__uint_as_float(v0), __uint_as_float(v1),
                                    __uint_as_float(v2), __uint_as_float(v3));
            *(float4*)&hs[PADIDX(tid * 4)] = hv;
            __syncthreads();   // barrier A: all 512 h values staged
        }

        // Matvec: 4 gate rows x 16 cols per lane
        float hv16[16];
        const float* hrow = &hs[20 * l];
#pragma unroll
        for (int kk = 0; kk < 16; kk += 4)
            *(float4*)(hv16 + kk) = *(const float4*)(hrow + kk);

        float a0 = 0.f, a1 = 0.f, a2 = 0.f, a3 = 0.f;
#pragma unroll
        for (int kk = 0; kk < 16; kk++) {
            a0 = fmaf(wt[0][kk], hv16[kk], a0);
            a1 = fmaf(wt[1][kk], hv16[kk], a1);
            a2 = fmaf(wt[2][kk], hv16[kk], a2);
            a3 = fmaf(wt[3][kk], hv16[kk], a3);
        }
        // Full butterfly: all lanes end with the complete 4 gate sums
#pragma unroll
        for (int off = 16; off >= 1; off >>= 1) {
            a0 += __shfl_xor_sync(0xffffffffu, a0, off);
            a1 += __shfl_xor_sync(0xffffffffu, a1, off);
            a2 += __shfl_xor_sync(0xffffffffu, a2, off);
            a3 += __shfl_xor_sync(0xffffffffu, a3, off);
        }

        // Lanes 0-3 apply their gate's activation in parallel (MUFU path)
        float act = 0.0f;
        if (xlane) {
            float pre = (l == 0 ? a0 : l == 1 ? a1 : l == 2 ? a2 : a3) + xg_cur;
            act = (l == 2) ? tanh_fast(pre) : sigmoid_fast(pre);
        }
        float iv = __shfl_sync(0xffffffffu, act, 0);
        float fv = __shfl_sync(0xffffffffu, act, 1);
        float gv = __shfl_sync(0xffffffffu, act, 2);
        float ov = __shfl_sync(0xffffffffu, act, 3);

        if (l == 0) {
            c_state = fv * c_state + iv * gv;
            float hval = ov * tanh_fast(c_state);
            // Force mantissa LSB = parity(t); |perturbation| <= 2^-24 rel.
            unsigned int hb = (__float_as_uint(hval) & ~1u) |
                              (((unsigned int)t >> 1) & 1u);
            float hpub = __uint_as_float(hb);
            st_relaxed_u32(&g_hpar[t & 1][gu], hb);   // 4B publish = the signal
            out[(size_t)t * HDIM + gu] = hpub;        // consistent trajectory
        }
        xg_cur = xg_nxt;
        __syncthreads();   // trailing barrier: re-aligns warps each step
    }
}

// ---------------------------------------------------------------------------
extern "C" void kernel_launch(void* const* d_in, const int* in_sizes, int n_in,
                              void* d_out, int out_size) {
    const float* input = (const float*)d_in[0];  // [T, H]
    const float* w_ih  = (const float*)d_in[1];  // [4H, H]
    const float* w_hh  = (const float*)d_in[2];  // [4H, H]
    const float* b_ih  = (const float*)d_in[3];  // [4H]
    float* out = (float*)d_out;                  // [T, H]
    (void)in_sizes; (void)n_in; (void)out_size;

    init_ring_kernel<<<4, 256>>>();

    dim3 gg(G4 / 128, T_SEQ / 128);              // 16 x 128 blocks
    gemm_xgates_kernel<<<gg, 256>>>(input, w_ih, b_ih);

    lstm_rec_kernel<<<NB, 128>>>(w_hh, out);
}